// round 17
// baseline (speedup 1.0000x reference)
#include <cuda_runtime.h>
#include <math.h>
#include <stdint.h>

#define Kk 256
#define Tt 512
#define NBb 256
#define Vv 4096

#define NT 512
#define NC (NBb/2)      // 128 CTAs, 2 sequences each

// 16 warps = 2 (p: state half) x 8 (q: i-slice). Warp (p,q): output states
// {128p + 32m + lane, m=0..3}, summation i in [32q, 32q+32).
// Per thread: 4 states x 32 i = 64 u64 pairs; 32 in regs (c=0..7 per state),
// 32 via smem (c=8..15). 4 warps/SMSP for latency hiding.
// Tail: thread (s = tid>>8, j = tid&255) handles ONE sequence's state j.

typedef unsigned long long ull;

// ---------------- device scratch ----------------
__device__ ull  g_Freg[32*NT];     // forward  A-pack, register part
__device__ ull  g_Fsm [32*NT];     // forward  A-pack, smem part
__device__ ull  g_Breg[32*NT];     // backward A-pack, register part
__device__ ull  g_Bsm [32*NT];     // backward A-pack, smem part
__device__ float g_Bt[Vv*Kk];      // exp(log_B) transposed: [v][j]
__device__ float g_pi[Kk];

// ---------------- prep ----------------
__global__ void prep_pack(const float* __restrict__ logA, const float* __restrict__ logpi) {
    int idx = blockIdx.x * blockDim.x + threadIdx.x;   // 0 .. 32767
    if (idx < Kk) g_pi[idx] = expf(logpi[idx]);
    int tid = idx & 511;
    int k   = idx >> 9;            // 0..63 : k = m*16 + c
    int m = k >> 4, c = k & 15;
    int wi = tid >> 5, l = tid & 31;
    int p = wi >> 3, q = wi & 7;
    int j = 128*p + 32*m + l;      // output state
    int i = 32*q + 2*c;            // summation index (pair base)
    float f0 = expf(logA[i*Kk + j]);        // fwd: sum_i e[i]*A[i][j]
    float f1 = expf(logA[(i+1)*Kk + j]);
    float b0 = expf(logA[j*Kk + i]);        // bwd: sum_i e[i]*A[j][i]
    float b1 = expf(logA[j*Kk + i + 1]);
    ull fv = ((ull)__float_as_uint(f1) << 32) | __float_as_uint(f0);
    ull bv = ((ull)__float_as_uint(b1) << 32) | __float_as_uint(b0);
    if (c < 8) {
        g_Freg[(m*8 + c)*NT + tid] = fv;
        g_Breg[(m*8 + c)*NT + tid] = bv;
    } else {
        int cc = c - 8;            // 0..7 -> ulonglong2 hh = cc>>1, parity cc&1
        int u = (((m*4 + (cc>>1))*NT + tid) << 1) | (cc & 1);
        g_Fsm[u] = fv;
        g_Bsm[u] = bv;
    }
}

__global__ void prep_B(const float* __restrict__ logB) {
    int idx = blockIdx.x * blockDim.x + threadIdx.x;   // j*Vv + v (coalesced read)
    if (idx >= Kk*Vv) return;
    int j = idx / Vv, v = idx % Vv;
    g_Bt[v*Kk + j] = expf(logB[idx]);
}

// ---------------- helpers ----------------
__device__ __forceinline__ void ffma2(ull& d, ull a, ull b) {
    asm("fma.rn.f32x2 %0, %1, %2, %0;" : "+l"(d) : "l"(a), "l"(b));
}
__device__ __forceinline__ void fadd2(ull& d, ull a) {
    asm("add.rn.f32x2 %0, %0, %1;" : "+l"(d) : "l"(a));
}
__device__ __forceinline__ float psum1(ull a) {
    unsigned lo, hi; asm("mov.b64 {%0,%1}, %2;" : "=r"(lo), "=r"(hi) : "l"(a));
    return __uint_as_float(lo) + __uint_as_float(hi);
}

// split-K dot: warp covers i in [32q,32q+32) for its 4 states, both seqs.
// Also accumulates the slice-sum of seq p's e-slice -> ssum[p*8+q].
__device__ __forceinline__ void do_dot(const ull (&ra)[32],
                                       const ull* __restrict__ As2,
                                       const float* __restrict__ es,   // [2][Kk]
                                       float* __restrict__ part,       // [2s][8q][256j]
                                       float* __restrict__ ssum,       // [2][8]
                                       int p, int q, int l, int tid) {
    const ulonglong2* e0 = reinterpret_cast<const ulonglong2*>(es + 32*q);
    const ulonglong2* e1 = reinterpret_cast<const ulonglong2*>(es + Kk + 32*q);
    ull acc[4][2] = {};
    ull cs = 0;
    // register half: e pairs 0..7 (ulonglong2 0..3)
    #pragma unroll
    for (int h = 0; h < 4; h++) {
        ulonglong2 v0 = e0[h], v1 = e1[h];
        if (p == 0) { fadd2(cs, v0.x); fadd2(cs, v0.y); }
        else        { fadd2(cs, v1.x); fadd2(cs, v1.y); }
        #pragma unroll
        for (int m = 0; m < 4; m++) {
            ffma2(acc[m][0], ra[m*8 + 2*h],     v0.x);
            ffma2(acc[m][0], ra[m*8 + 2*h + 1], v0.y);
            ffma2(acc[m][1], ra[m*8 + 2*h],     v1.x);
            ffma2(acc[m][1], ra[m*8 + 2*h + 1], v1.y);
        }
    }
    // smem half: e pairs 8..15 (ulonglong2 4..7)
    const ulonglong2* Asv = reinterpret_cast<const ulonglong2*>(As2);
    #pragma unroll
    for (int h = 0; h < 4; h++) {
        ulonglong2 v0 = e0[4 + h], v1 = e1[4 + h];
        if (p == 0) { fadd2(cs, v0.x); fadd2(cs, v0.y); }
        else        { fadd2(cs, v1.x); fadd2(cs, v1.y); }
        #pragma unroll
        for (int m = 0; m < 4; m++) {
            ulonglong2 av = Asv[(m*4 + h)*NT + tid];
            ffma2(acc[m][0], av.x, v0.x);
            ffma2(acc[m][0], av.y, v0.y);
            ffma2(acc[m][1], av.x, v1.x);
            ffma2(acc[m][1], av.y, v1.y);
        }
    }
    #pragma unroll
    for (int m = 0; m < 4; m++) {
        int j = 128*p + 32*m + l;
        part[q*256 + j]        = psum1(acc[m][0]);
        part[2048 + q*256 + j] = psum1(acc[m][1]);
    }
    if (l == 0) ssum[p*8 + q] = psum1(cs);
}

// ---------------- main persistent kernel ----------------
__global__ void __launch_bounds__(NT, 1)
hmm_fb(const int* __restrict__ obs, float* __restrict__ out) {
    extern __shared__ float sm[];
    ull*   As2   = (ull*)sm;                    // 32*NT u64 = 128KB
    float* part  = (float*)(As2 + 32*NT);       // [2][8][256] = 16KB
    float* es    = part + 2*2048;               // [2][Kk]
    float* ssum  = es + 2*Kk;                   // [2][8]
    int*   obs_s = (int*)(ssum + 16);           // [2][Tt]

    const int tid = threadIdx.x, wi = tid >> 5, l = tid & 31;
    const int p = wi >> 3, q = wi & 7;
    const int n0 = 2*blockIdx.x;
    const int s = tid >> 8, j = tid & 255;      // tail identity: (sequence, state)

    for (int i = tid; i < 2*Tt; i += NT) {
        int seq = i >> 9, tt = i & 511;
        obs_s[i] = obs[(n0 + seq)*Tt + tt];
    }

    ull ra[32];
    #pragma unroll
    for (int k = 0; k < 32; k++) ra[k] = g_Freg[k*NT + tid];
    {
        const ulonglong2* src = reinterpret_cast<const ulonglong2*>(g_Fsm);
        ulonglong2*       dst = reinterpret_cast<ulonglong2*>(As2);
        #pragma unroll
        for (int k = 0; k < 16; k++) dst[k*NT + tid] = src[k*NT + tid];
    }
    __syncthreads();        // obs_s (and A-cache) published before any read

    float* outp = out + (size_t)(n0 + s)*Tt*Kk + j;    // my (seq, state) column
    const int* obss = obs_s + s*Tt;
    float w;

    // ---- forward init (t = 0) ----
    {
        w = g_pi[j] * g_Bt[obss[0]*Kk + j];
        es[s*Kk + j] = w;
        __syncthreads();    // es published
    }

    // ---- forward loop ----
    for (int t = 1; t < Tt; t++) {
        float bb = g_Bt[obss[t]*Kk + j];               // prefetch, hidden by dot
        do_dot(ra, As2, es, part, ssum, p, q, l, tid);
        __syncthreads();                               // part + ssum ready
        const float* sb = ssum + s*8;
        float r = __fdividef(1.f, ((sb[0]+sb[1]) + (sb[2]+sb[3]))
                                + ((sb[4]+sb[5]) + (sb[6]+sb[7])));
        const float* pb = part + s*2048 + j;
        float u = 0.f;
        #pragma unroll
        for (int k = 0; k < 8; k++) u += pb[k*256];
        outp[(size_t)(t-1)*Kk] = w * r;                // normalized p_{t-1}
        w = u * r * bb;
        es[s*Kk + j] = w;
        __syncthreads();                               // es ready for next dot
    }
    // last row: any per-row scale works (epilogue renormalizes)
    outp[(size_t)(Tt-1)*Kk] = w;
    __syncthreads();

    // ---- reload A-pack for backward ----
    #pragma unroll
    for (int k = 0; k < 32; k++) ra[k] = g_Breg[k*NT + tid];
    {
        const ulonglong2* src = reinterpret_cast<const ulonglong2*>(g_Bsm);
        ulonglong2*       dst = reinterpret_cast<ulonglong2*>(As2);
        #pragma unroll
        for (int k = 0; k < 16; k++) dst[k*NT + tid] = src[k*NT + tid];
    }

    // ---- backward init: y_{T-1} = B[:,o_{T-1}] (beta = 1) ----
    {
        es[s*Kk + j] = g_Bt[obss[Tt-1]*Kk + j];
        __syncthreads();    // es + rewritten A-cache published
    }

    // ---- backward loop ----
    for (int t = Tt - 2; t >= 0; t--) {
        float pp = outp[(size_t)t*Kk];                 // prefetch p_t
        float bb = g_Bt[obss[t]*Kk + j];
        do_dot(ra, As2, es, part, ssum, p, q, l, tid);
        __syncthreads();
        const float* sb = ssum + s*8;
        float r = __fdividef(1.f, ((sb[0]+sb[1]) + (sb[2]+sb[3]))
                                + ((sb[4]+sb[5]) + (sb[6]+sb[7])));
        const float* pb = part + s*2048 + j;
        float u = 0.f;
        #pragma unroll
        for (int k = 0; k < 8; k++) u += pb[k*256];
        float be = u * r;                              // scaled beta_t
        outp[(size_t)t*Kk] = pp * be;                  // unnormalized gamma
        es[s*Kk + j] = be * bb;                        // y_t = bb_t . beta_t
        __syncthreads();
    }
}

// ---------------- epilogue: per-(n,t) log-normalize ----------------
__global__ void __launch_bounds__(256)
norm_gamma(float* __restrict__ out) {
    int row  = (blockIdx.x << 3) + (threadIdx.x >> 5);
    int lane = threadIdx.x & 31;
    float4* p = reinterpret_cast<float4*>(out + (size_t)row * Kk);
    float4 v0 = p[lane], v1 = p[lane + 32];
    float s = v0.x + v0.y + v0.z + v0.w + v1.x + v1.y + v1.z + v1.w;
    #pragma unroll
    for (int o = 16; o; o >>= 1) s += __shfl_xor_sync(0xFFFFFFFFu, s, o);
    float lc = __logf(s);
    v0.x = __logf(v0.x) - lc; v0.y = __logf(v0.y) - lc;
    v0.z = __logf(v0.z) - lc; v0.w = __logf(v0.w) - lc;
    v1.x = __logf(v1.x) - lc; v1.y = __logf(v1.y) - lc;
    v1.z = __logf(v1.z) - lc; v1.w = __logf(v1.w) - lc;
    p[lane] = v0; p[lane + 32] = v1;
}

// ---------------- launch ----------------
extern "C" void kernel_launch(void* const* d_in, const int* in_sizes, int n_in,
                              void* d_out, int out_size) {
    const float* log_pi = (const float*)d_in[0];
    const float* log_A  = (const float*)d_in[1];
    const float* log_B  = (const float*)d_in[2];
    const int*   observ = (const int*)  d_in[3];
    float* out = (float*)d_out;

    const int smem_bytes = 32*NT*8 + (2*2048 + 2*Kk + 16)*4 + 2*Tt*4;
    cudaFuncSetAttribute(hmm_fb, cudaFuncAttributeMaxDynamicSharedMemorySize, smem_bytes);

    prep_pack<<<128, 256>>>(log_A, log_pi);
    prep_B<<<(Kk*Vv + 255)/256, 256>>>(log_B);
    hmm_fb<<<NC, NT, smem_bytes>>>(observ, out);
    norm_gamma<<<(NBb*Tt)/8, 256>>>(out);
}